// round 16
// baseline (speedup 1.0000x reference)
#include <cuda_runtime.h>
#include <cuda_fp16.h>
#include <math.h>
#include <stdint.h>

#define BATCH 16
#define SEQ   1024
#define DM    512
#define HD    64
#define DFF   2048
#define MTOT  (BATCH*SEQ)   // 16384
#define NLAYERS 4

// ---------------- scratch (static device globals; no allocation) -------------
__device__ __half g_xh[MTOT*DM];                   // fp16 trunk (GEMM A + resid)
__device__ __half g_qkvh[MTOT*192];                // q|k|v fp16
__device__ __half g_Eh[(size_t)BATCH*SEQ*SEQ];     // exp(scores) fp16, 32 MB
__device__ float  g_rs[MTOT];                      // colsum accumulators
__device__ __half g_vt[BATCH*HD*SEQ];              // (v*(1024/sum))^T per batch
__device__ __half g_headh[MTOT*128];               // two K-split partials
__device__ float  g_t1[MTOT*DM];
__device__ __half g_hh[MTOT*DM];                   // fp16 h (FF A + resid)
__device__ float  g_t2[MTOT*DM];
__device__ __half g_wqkvT[192*DM];                 // [192][512]
__device__ float  g_bqkv[192];
__device__ __half g_weffT2[DM*128];                // duplicated weff^T [512][128]
__device__ __half g_w1h[DM*DFF];                   // w1 row-major fp16
__device__ __half g_w2t[DM*DFF];                   // w2^T [512][2048]
__device__ __half g_W12T[DM*DM];                   // (w1@w2)^T fp16 [n][k]
__device__ float  g_bff[DM];                       // b1@w2 + b2

__device__ __forceinline__ void cpasync16(uint32_t s, const void* g) {
    asm volatile("cp.async.cg.shared.global [%0], [%1], 16;" :: "r"(s), "l"(g));
}

// ---------------- fp16 tensor-core GEMM (m16n8k16), 2-stage pipeline ---------
// C[M,ldc] = A[M,lda] @ B^T + bias (+fp16 resid). A:[m][k] fp16, B:[n][k] fp16.
// Epilogue: v = acc*oscale; EXPSC: store 2^v as fp16 via ex2.approx.f16x2;
// else +bias/+resid, store fp16 (OUTH) or f32. COLSUM: per-column atomic sums.
// ZRS: blocks with blockIdx.x==0 zero csout[m0..m0+127].
// KSPLIT>1: blockIdx.x selects a K-chunk of size K; output cols shift by
// blockIdx.x*BN (concat-split-K: consumer uses duplicated B to re-sum).
template<int BN, bool HASBIAS, bool RES, bool EXPSC, bool OUTH, bool COLSUM,
         bool ZRS, int KSPLIT>
__global__ __launch_bounds__(256, 2)
void mm_h(const __half* __restrict__ A, const __half* __restrict__ B,
          const float* __restrict__ bias, const __half* __restrict__ resid,
          __half* __restrict__ Ch, float* __restrict__ Cf,
          float* __restrict__ csout,
          int K, int lda, int ldb, int ldc, float oscale,
          long long sA, long long sB, long long sC)
{
    constexpr int BM = 128, BK = 32, BKP = 40;
    constexpr int WN = BN / 2;       // warp n-extent (2 warp cols)
    constexpr int NF = WN / 8;       // n-fragments per warp
    constexpr int BCH = (BK * BN) / 8;   // B stage chunks (16B each)
    __shared__ __align__(16) __half As[2][BM][BKP];
    __shared__ __align__(16) __half Bs[2][BN][BKP];

    const int tid  = threadIdx.x;
    const int lane = tid & 31, warp = tid >> 5;
    const int wr = warp & 3, wc = warp >> 2;
    const int g = lane >> 2, q = lane & 3;
    const int m0 = blockIdx.y * BM;
    const int n0   = (KSPLIT > 1) ? 0 : blockIdx.x * BN;
    const int kofs = (KSPLIT > 1) ? blockIdx.x * K : 0;
    const int cbase= (KSPLIT > 1) ? blockIdx.x * BN : n0;
    const int z  = blockIdx.z;
    const __half* Ab = A + (size_t)z * sA;
    const __half* Bb = B + (size_t)z * sB;

    if (ZRS && blockIdx.x == 0 && tid < BM)
        csout[(size_t)(m0 + tid)] = 0.f;

    auto stage = [&](int t, int s) {
        const int k0 = kofs + t * BK;
        #pragma unroll
        for (int p = 0; p < 2; p++) {                 // A: 128x32 halves = 512 x 16B
            int c = tid + p * 256;
            int r = c >> 2, kc = (c & 3) << 3;
            uint32_t sa = (uint32_t)__cvta_generic_to_shared(&As[s][r][kc]);
            cpasync16(sa, Ab + (size_t)(m0 + r) * lda + k0 + kc);
        }
        #pragma unroll
        for (int p = 0; p < (BCH + 255) / 256; p++) { // B: BNx32 halves
            int c = tid + p * 256;
            if (BCH % 256 == 0 || c < BCH) {
                int r = c >> 2, kc = (c & 3) << 3;
                uint32_t sa = (uint32_t)__cvta_generic_to_shared(&Bs[s][r][kc]);
                cpasync16(sa, Bb + (size_t)(n0 + r) * ldb + k0 + kc);
            }
        }
        asm volatile("cp.async.commit_group;");
    };

    float acc[2][NF][4];
    #pragma unroll
    for (int i = 0; i < 2; i++)
        #pragma unroll
        for (int j = 0; j < NF; j++)
            #pragma unroll
            for (int c = 0; c < 4; c++) acc[i][j][c] = 0.f;

    const int mw = wr * 32;
    const int nw = wc * WN;
    const int T = K / BK;

    stage(0, 0);
    for (int t = 0; t < T; t++) {
        if (t + 1 < T) { stage(t + 1, (t + 1) & 1); asm volatile("cp.async.wait_group 1;"); }
        else           { asm volatile("cp.async.wait_group 0;"); }
        __syncthreads();
        const int s = t & 1;
        #pragma unroll
        for (int ks = 0; ks < BK; ks += 16) {
            uint32_t af[2][4];
            #pragma unroll
            for (int i = 0; i < 2; i++) {
                af[i][0] = *(const uint32_t*)&As[s][mw + i*16 + g    ][ks + 2*q    ];
                af[i][1] = *(const uint32_t*)&As[s][mw + i*16 + g + 8][ks + 2*q    ];
                af[i][2] = *(const uint32_t*)&As[s][mw + i*16 + g    ][ks + 2*q + 8];
                af[i][3] = *(const uint32_t*)&As[s][mw + i*16 + g + 8][ks + 2*q + 8];
            }
            uint32_t bf[NF][2];
            #pragma unroll
            for (int j = 0; j < NF; j++) {
                int n = nw + j * 8 + g;
                bf[j][0] = *(const uint32_t*)&Bs[s][n][ks + 2*q    ];
                bf[j][1] = *(const uint32_t*)&Bs[s][n][ks + 2*q + 8];
            }
            #pragma unroll
            for (int i = 0; i < 2; i++)
                #pragma unroll
                for (int j = 0; j < NF; j++)
                    asm volatile(
                        "mma.sync.aligned.m16n8k16.row.col.f32.f16.f16.f32 "
                        "{%0,%1,%2,%3}, {%4,%5,%6,%7}, {%8,%9}, {%0,%1,%2,%3};"
                        : "+f"(acc[i][j][0]), "+f"(acc[i][j][1]),
                          "+f"(acc[i][j][2]), "+f"(acc[i][j][3])
                        : "r"(af[i][0]), "r"(af[i][1]), "r"(af[i][2]), "r"(af[i][3]),
                          "r"(bf[j][0]), "r"(bf[j][1]));
        }
        __syncthreads();
    }

    float cs[COLSUM ? NF : 1][2];
    if (COLSUM)
        #pragma unroll
        for (int j = 0; j < NF; j++) { cs[j][0] = 0.f; cs[j][1] = 0.f; }

    #pragma unroll
    for (int i = 0; i < 2; i++) {
        #pragma unroll
        for (int j = 0; j < NF; j++) {
            int col = cbase + nw + j * 8 + 2 * q;
            #pragma unroll
            for (int hh = 0; hh < 2; hh++) {
                size_t row = (size_t)(m0 + mw + i * 16 + g + hh * 8);
                float v0 = acc[i][j][hh * 2 + 0] * oscale;
                float v1 = acc[i][j][hh * 2 + 1] * oscale;
                if (EXPSC) {
                    // E = 2^(s*log2e/8): one MUFU op per two elements
                    __half2 ah = __floats2half2_rn(v0, v1);
                    uint32_t eu;
                    asm("ex2.approx.f16x2 %0, %1;" : "=r"(eu) : "r"(*(uint32_t*)&ah));
                    *(uint32_t*)&(Ch + (size_t)z * sC)[row * ldc + col] = eu;
                    if (COLSUM) {
                        float2 ef = __half22float2(*(__half2*)&eu);
                        cs[j][0] += ef.x; cs[j][1] += ef.y;
                    }
                } else {
                    if (HASBIAS){ v0 += bias[col]; v1 += bias[col + 1]; }
                    if (RES) {
                        __half2 rv = *(const __half2*)&resid[row * ldc + col];
                        float2 rf = __half22float2(rv);
                        v0 += rf.x; v1 += rf.y;
                    }
                    if (OUTH) {
                        __half2 hv = __floats2half2_rn(v0, v1);
                        *(uint32_t*)&(Ch + (size_t)z * sC)[row * ldc + col] =
                            *(uint32_t*)&hv;
                    } else {
                        *(float2*)&(Cf + (size_t)z * sC)[row * ldc + col] =
                            make_float2(v0, v1);
                    }
                }
            }
        }
    }

    if (COLSUM) {
        #pragma unroll
        for (int j = 0; j < NF; j++) {
            #pragma unroll
            for (int c = 0; c < 2; c++) {
                float v = cs[j][c];
                v += __shfl_xor_sync(0xffffffffu, v, 4);
                v += __shfl_xor_sync(0xffffffffu, v, 8);
                v += __shfl_xor_sync(0xffffffffu, v, 16);
                if (g == 0)
                    atomicAdd(&csout[(size_t)z * SEQ + n0 + nw + j * 8 + 2 * q + c], v);
            }
        }
    }
}

// ---------------- vt[b][d][key] = v[b,key,d] * 1024/sum (smem transpose) -----
__global__ __launch_bounds__(256)
void scalevt_k(const __half* __restrict__ qkv, const float* __restrict__ rs,
               __half* __restrict__ vt)
{
    __shared__ __align__(16) __half sm[64][72];   // 144B row stride: uint4-safe
    __shared__ float rsm[64];
    const int b = blockIdx.y;
    const int key0 = blockIdx.x * 64;
    const int tid = threadIdx.x;
    #pragma unroll
    for (int p = 0; p < 2; p++) {
        int c = tid + p * 256;                 // 512 chunks of 8 halves
        int kr = c >> 3, d8 = (c & 7) << 3;
        *(uint4*)&sm[kr][d8] =
            *(const uint4*)&qkv[((size_t)(b * SEQ + key0 + kr)) * 192 + 128 + d8];
    }
    if (tid < 64) rsm[tid] = 1024.f / rs[b * SEQ + key0 + tid];
    __syncthreads();
    #pragma unroll
    for (int p = 0; p < 2; p++) {
        int c = tid + p * 256;
        int d = c >> 3, k8 = (c & 7) << 3;
        uint4 o;
        uint32_t* ow = (uint32_t*)&o;
        #pragma unroll
        for (int i = 0; i < 4; i++) {
            float f0 = __half2float(sm[k8 + 2*i    ][d]) * rsm[k8 + 2*i    ];
            float f1 = __half2float(sm[k8 + 2*i + 1][d]) * rsm[k8 + 2*i + 1];
            __half2 hv = __floats2half2_rn(f0, f1);
            ow[i] = *(uint32_t*)&hv;
        }
        *(uint4*)&vt[((size_t)(b * HD + d)) * SEQ + key0 + k8] = o;
    }
}

// ---------------- LayerNorm: warp-per-row, 8 rows/block ----------------------
template<bool F32OUT>
__global__ __launch_bounds__(256)
void ln_kernel(const float* __restrict__ in, const float* __restrict__ gamma,
               const float* __restrict__ beta, float* __restrict__ outf,
               __half* __restrict__ outh)
{
    const int warp = threadIdx.x >> 5, lane = threadIdx.x & 31;
    const size_t row = (size_t)blockIdx.x * 8 + warp;
    const float4* ip = (const float4*)(in + row * DM);

    float4 v[4];
    float s = 0.f, ss = 0.f;
    #pragma unroll
    for (int i = 0; i < 4; i++) {
        v[i] = ip[lane + 32 * i];
        s  += v[i].x + v[i].y + v[i].z + v[i].w;
        ss += v[i].x*v[i].x + v[i].y*v[i].y + v[i].z*v[i].z + v[i].w*v[i].w;
    }
    #pragma unroll
    for (int o = 16; o > 0; o >>= 1) {
        s  += __shfl_xor_sync(0xffffffffu, s,  o);
        ss += __shfl_xor_sync(0xffffffffu, ss, o);
    }
    const float mu  = s * (1.f / DM);
    const float var = ss * (1.f / DM) - mu * mu;
    const float inv = rsqrtf(var + 1e-5f);

    #pragma unroll
    for (int i = 0; i < 4; i++) {
        float4 g = ((const float4*)gamma)[lane + 32 * i];
        float4 b = ((const float4*)beta)[lane + 32 * i];
        float4 o;
        o.x = (v[i].x - mu) * inv * g.x + b.x;
        o.y = (v[i].y - mu) * inv * g.y + b.y;
        o.z = (v[i].z - mu) * inv * g.z + b.z;
        o.w = (v[i].w - mu) * inv * g.w + b.w;
        if (F32OUT) {
            ((float4*)(outf + row * DM))[lane + 32 * i] = o;
        } else {
            __half2 h0 = __floats2half2_rn(o.x, o.y);
            __half2 h1 = __floats2half2_rn(o.z, o.w);
            *(uint2*)&outh[row * DM + (lane + 32 * i) * 4] =
                make_uint2(*(uint32_t*)&h0, *(uint32_t*)&h1);
        }
    }
}

// ---------------- prep kernels ----------------------------------------------
__global__ void prep_wqkv(const float* wq, const float* wk, const float* wv,
                          const float* bq, const float* bk, const float* bv,
                          __half* wT, float* bias)
{
    int idx = blockIdx.x * 256 + threadIdx.x;
    if (idx < DM * 192) {
        int c = idx / DM, r = idx % DM;
        float v = (c < 64) ? wq[r*64 + c] : (c < 128 ? wk[r*64 + c - 64] : wv[r*64 + c - 128]);
        wT[idx] = __float2half_rn(v);
    }
    if (idx < 192)
        bias[idx] = (idx < 64) ? bq[idx] : (idx < 128 ? bk[idx - 64] : bv[idx - 128]);
}

// weffT2[n][k] = sum_h wo[64h + (k&63)][n]   (n in [0,512), k in [0,128))
__global__ void prep_weff(const float* __restrict__ wo, __half* __restrict__ wT)
{
    int idx = blockIdx.x * 256 + threadIdx.x;
    if (idx < DM * 128) {
        int n = idx >> 7, k = idx & 127;
        int r = k & 63;
        float s = 0.f;
        #pragma unroll
        for (int h = 0; h < 8; h++) s += wo[(size_t)(h*HD + r) * DM + n];
        wT[idx] = __float2half_rn(s);
    }
}

// Tiled transpose W[R][C] -> T[C][R] fp16 (coalesced loads AND stores)
__global__ __launch_bounds__(256)
void prep_t(const float* __restrict__ W, __half* __restrict__ T, int R, int C)
{
    __shared__ __half sm[32][33];
    const int c0 = blockIdx.x * 32;
    const int r0 = blockIdx.y * 32;
    const int lx = threadIdx.x & 31, ly = threadIdx.x >> 5;   // 32 x 8
    #pragma unroll
    for (int i = 0; i < 4; i++) {
        int r = r0 + ly + i * 8;
        sm[ly + i * 8][lx] = __float2half_rn(W[(size_t)r * C + c0 + lx]);
    }
    __syncthreads();
    #pragma unroll
    for (int i = 0; i < 4; i++) {
        int c = c0 + ly + i * 8;
        T[(size_t)c * R + r0 + lx] = sm[lx][ly + i * 8];
    }
}

__global__ void cvt_h(const float* __restrict__ in, __half* __restrict__ out)
{
    int idx = blockIdx.x * 256 + threadIdx.x;   // one float4 -> half4 each
    float4 v = ((const float4*)in)[idx];
    __half2 h0 = __floats2half2_rn(v.x, v.y);
    __half2 h1 = __floats2half2_rn(v.z, v.w);
    ((uint2*)out)[idx] = make_uint2(*(uint32_t*)&h0, *(uint32_t*)&h1);
}

// bff[n] = b2[n] + sum_k b1[k] * w2[k][n]  — parallel over k-slices
__global__ __launch_bounds__(256)
void prep_bff(const float* __restrict__ b1, const float* __restrict__ w2,
              const float* __restrict__ b2, float* __restrict__ bff)
{
    __shared__ float sm[8][32];
    const int nloc = threadIdx.x & 31;
    const int slice = threadIdx.x >> 5;          // 8 slices x 256 k
    const int n = blockIdx.x * 32 + nloc;
    float s = 0.f;
    const int k0 = slice * 256;
    #pragma unroll 8
    for (int k = k0; k < k0 + 256; k++)
        s += b1[k] * w2[(size_t)k * DM + n];
    sm[slice][nloc] = s;
    __syncthreads();
    if (slice == 0) {
        float t = b2[n];
        #pragma unroll
        for (int r = 0; r < 8; r++) t += sm[r][nloc];
        bff[n] = t;
    }
}

// ---------------- host orchestration ----------------------------------------
extern "C" void kernel_launch(void* const* d_in, const int* in_sizes, int n_in,
                              void* d_out, int out_size)
{
    (void)in_sizes; (void)n_in; (void)out_size;
    const float* x   = (const float*)d_in[0];
    const float* wq  = (const float*)d_in[1];
    const float* bq  = (const float*)d_in[2];
    const float* wk  = (const float*)d_in[3];
    const float* bk  = (const float*)d_in[4];
    const float* wv  = (const float*)d_in[5];
    const float* bv  = (const float*)d_in[6];
    const float* wo  = (const float*)d_in[7];
    const float* bo  = (const float*)d_in[8];
    const float* lng = (const float*)d_in[9];
    const float* lnb = (const float*)d_in[10];
    const float* w1  = (const float*)d_in[11];
    const float* b1  = (const float*)d_in[12];
    const float* w2  = (const float*)d_in[13];
    const float* b2  = (const float*)d_in[14];
    float* out = (float*)d_out;

    __half *xh, *qkvh, *Eh, *vt, *headh, *hh, *wqkvT, *weffT2, *w1h, *w2t, *W12T;
    float *rs, *t1, *t2, *bqkvD, *bffD;
    cudaGetSymbolAddress((void**)&xh,    g_xh);
    cudaGetSymbolAddress((void**)&qkvh,  g_qkvh);
    cudaGetSymbolAddress((void**)&Eh,    g_Eh);
    cudaGetSymbolAddress((void**)&rs,    g_rs);
    cudaGetSymbolAddress((void**)&vt,    g_vt);
    cudaGetSymbolAddress((void**)&headh, g_headh);
    cudaGetSymbolAddress((void**)&t1,    g_t1);
    cudaGetSymbolAddress((void**)&hh,    g_hh);
    cudaGetSymbolAddress((void**)&t2,    g_t2);
    cudaGetSymbolAddress((void**)&wqkvT, g_wqkvT);
    cudaGetSymbolAddress((void**)&bqkvD, g_bqkv);
    cudaGetSymbolAddress((void**)&weffT2, g_weffT2);
    cudaGetSymbolAddress((void**)&w1h,   g_w1h);
    cudaGetSymbolAddress((void**)&w2t,   g_w2t);
    cudaGetSymbolAddress((void**)&W12T,  g_W12T);
    cudaGetSymbolAddress((void**)&bffD,  g_bff);

    // prep: transpose/convert weights, fold FF weights, fp16 input copy
    prep_wqkv<<<(DM*192 + 255)/256, 256>>>(wq, wk, wv, bq, bk, bv, wqkvT, bqkvD);
    prep_weff<<<(DM*128 + 255)/256, 256>>>(wo, weffT2);
    cvt_h<<<(DM*DFF/4)/256, 256>>>(w1, w1h);
    prep_t<<<dim3(DM/32, DFF/32), 256>>>(w2, w2t, DFF, DM);
    prep_bff<<<DM/32, 256>>>(b1, w2, b2, bffD);
    cvt_h<<<((size_t)MTOT*DM/4)/256, 256>>>(x, xh);

    // W12T[n][m] = sum_k w2t[n][k] * w1h[m][k]  (=(w1@w2)^T, fp16)
    mm_h<64, false, false, false, true, false, false, 1><<<dim3(DM/64, DM/128), 256>>>(
        w2t, w1h, nullptr, nullptr, W12T, nullptr, nullptr,
        DFF, DFF, DFF, DM, 1.f, 0, 0, 0);

    const float EXPSCALE = 0.125f * 1.4426950408889634f;  // /8 * log2(e)

    for (int L = 0; L < NLAYERS; L++) {
        // fused QKV: [16384,192] = x @ Wqkv + bqkv -> fp16 ; also zeros rs
        // BN=96 -> grid 256 blocks = exactly one wave
        mm_h<96, true, false, false, true, false, true, 1><<<dim3(2, 128, 1), 256>>>(
            xh, wqkvT, bqkvD, nullptr, qkvh, nullptr, rs,
            DM, DM, DM, 192, 1.f, 0, 0, 0);

        // E = 2^(q@k^T * log2e/8) per batch -> fp16, with fused column sums
        mm_h<128, false, false, true, true, true, false, 1><<<dim3(8, 8, 16), 256>>>(
            qkvh, qkvh + 64, nullptr, nullptr, Eh, nullptr, rs,
            HD, 192, 192, SEQ, EXPSCALE,
            (long long)SEQ * 192, (long long)SEQ * 192, (long long)SEQ * SEQ);

        // vt = (v * 1024/sum)^T
        scalevt_k<<<dim3(SEQ/64, BATCH), 256>>>(qkvh, rs, vt);

        // head partials: split-K=2 over keys; partial s -> cols [64s,64s+64)
        mm_h<64, false, false, false, true, false, false, 2><<<dim3(2, 8, 16), 256>>>(
            Eh, vt, nullptr, nullptr, headh, nullptr, nullptr,
            SEQ/2, SEQ, SEQ, 128, 1.f / 1024.f,
            (long long)SEQ * SEQ, (long long)HD * SEQ, (long long)SEQ * 128);

        // t1 = [h1 h2] @ [weff;weff] + bo + x(fp16) ; h = LN(t1) -> fp16
        mm_h<128, true, true, false, false, false, false, 1><<<dim3(4, 128, 1), 256>>>(
            headh, weffT2, bo, xh, nullptr, t1, nullptr,
            128, 128, 128, DM, 1.f, 0, 0, 0);
        ln_kernel<false><<<MTOT/8, 256>>>(t1, lng, lnb, nullptr, hh);

        // folded FF: t2 = h @ W12 + bff + h(fp16)
        mm_h<128, true, true, false, false, false, false, 1><<<dim3(4, 128, 1), 256>>>(
            hh, W12T, bffD, hh, nullptr, t2, nullptr,
            DM, DM, DM, DM, 1.f, 0, 0, 0);

        if (L == NLAYERS - 1)
            ln_kernel<true><<<MTOT/8, 256>>>(t2, lng, lnb, out, nullptr);
        else
            ln_kernel<false><<<MTOT/8, 256>>>(t2, lng, lnb, nullptr, xh);
    }
}